// round 9
// baseline (speedup 1.0000x reference)
#include <cuda_runtime.h>

typedef unsigned long long u64;

#define HDIM  64
#define IDIM  8
#define KDIM  72          // 64 h + 8 x folded into one reduction
#define KK    36          // KDIM/2 packed steps
#define NTHR  512
#define NPAIR 16          // batch pairs per CTA
#define NB    32          // batches per CTA

// SMEM (dynamic):
//  wsm[k=72][j=256] u64 pre-packed (w,w)        : 147456 B
//  hx[2][16][72] u64 (h units 0..63, x 64..71)  :  18432 B
//  gexch[4][512] u64 (gate exchange)            :  16384 B
#define WSM_BYTES   (KDIM * 256 * 8)
#define HX_BYTES    (2 * NPAIR * KDIM * 8)
#define GEX_BYTES   (4 * NTHR * 8)
#define SMEM_BYTES  (WSM_BYTES + HX_BYTES + GEX_BYTES)

// ---- packed f32x2 helpers (Blackwell sm_100a) ----
__device__ __forceinline__ u64 ffma2(u64 a, u64 b, u64 c) {
    u64 r;
    asm("fma.rn.f32x2 %0, %1, %2, %3;" : "=l"(r) : "l"(a), "l"(b), "l"(c));
    return r;
}
__device__ __forceinline__ u64 pack2(float x, float y) {
    u64 r;
    asm("mov.b64 %0, {%1, %2};" : "=l"(r) : "f"(x), "f"(y));
    return r;
}
__device__ __forceinline__ void unpack2(u64 v, float& lo, float& hi) {
    asm("mov.b64 {%0, %1}, %2;" : "=f"(lo), "=f"(hi) : "l"(v));
}

// ---- activations: __expf is MUFU-based, ~1e-7 rel err ----
__device__ __forceinline__ float sigm_f(float x) {
    return 1.0f / (1.0f + __expf(-x));
}
__device__ __forceinline__ float tanh_f(float x) {
    return fmaf(2.0f, 1.0f / (1.0f + __expf(-2.0f * x)), -1.0f);
}

__global__ void __launch_bounds__(NTHR, 1) lstm_persistent_kernel(
    const float* __restrict__ x,      // [B, T, I]
    const float* __restrict__ Wih,    // [4H, I]
    const float* __restrict__ Whh,    // [4H, H]
    const float* __restrict__ bih,    // [4H]
    const float* __restrict__ bhh,    // [4H]
    const float* __restrict__ Wfc,    // [1, H]
    const float* __restrict__ bfc,    // [1]
    float* __restrict__ out,          // [B, 1]
    int B, int T)
{
    extern __shared__ __align__(16) char smem_raw[];
    u64* wsm   = (u64*)smem_raw;                             // [k*256 + j], (w,w)
    u64* hxb   = (u64*)(smem_raw + WSM_BYTES);               // [buf][pair][KDIM]
    u64* gexch = (u64*)(smem_raw + WSM_BYTES + HX_BYTES);    // [slot*NTHR + tid]

    const int tid = threadIdx.x;
    // warp-uniform decomposition: warp holds 32 consecutive u, fixed gh/q
    const int gh  = (tid >> 5) & 1;                       // gate half: 0 -> (i,f), 1 -> (g,o)
    const int u   = (tid & 31) | (((tid >> 6) & 1) << 5); // hidden unit 0..63
    const int q   = tid >> 7;                             // pair group 0..3 (pairs 4q..4q+3)
    const int g0  = u + 128 * gh;                         // first gate row
    const int g1  = u + 64 + 128 * gh;                    // second gate row
    const int b0  = blockIdx.x * NB;
    const int nb  = min(NB, B - b0);
    const int nx  = nb * IDIM;

    // ---- stage combined W = [Whh | Wih] pre-packed (w,w): wsm[k][j] ----
    for (int idx = tid; idx < KDIM * 256; idx += NTHR) {
        const int k = idx >> 8, j = idx & 255;
        float w = (k < HDIM) ? Whh[j * HDIM + k] : Wih[j * IDIM + (k - HDIM)];
        wsm[idx] = pack2(w, w);
    }

    // ---- per-thread biases for the two owned gate rows ----
    const float bs0 = bih[g0] + bhh[g0];
    const float bs1 = bih[g1] + bhh[g1];
    const u64 bias0 = pack2(bs0, bs0);
    const u64 bias1 = pack2(bs1, bs1);

    // ---- zero hx (both buffers; phantom batches stay bounded) ----
    for (int idx = tid; idx < 2 * NPAIR * KDIM; idx += NTHR) hxb[idx] = 0ull;

    // ---- cell state for own pairs (2 pairs x 2 batches) ----
    const int oi = 2 * gh;         // own local pair idx base (pairs 4q+oi, 4q+oi+1)
    const int fi = 2 * (1 - gh);   // foreign local pair idx base
    float cc[2][2];
    cc[0][0] = cc[0][1] = cc[1][0] = cc[1][1] = 0.0f;

    // ---- load x(t=0): 256 scalars (32 batches x 8 features) ----
    int xp = 0, xe = 0, xi = 0;
    if (tid < nx) {
        xp = tid >> 4;            // pair 0..15
        xe = (tid >> 3) & 1;      // half within pair
        xi = tid & 7;             // feature
        float v = x[((size_t)(b0 + 2 * xp + xe) * T) * IDIM + xi];
        ((float*)&hxb[xp * KDIM + HDIM + xi])[xe] = v;
    }
    __syncthreads();

    for (int t = 0; t < T; ++t) {
        // prefetch x(t+1)
        float xn = 0.0f;
        const bool do_x = (t + 1 < T) && (tid < nx);
        if (do_x)
            xn = x[((size_t)(b0 + 2 * xp + xe) * T + (t + 1)) * IDIM + xi];

        const u64* hcur = hxb + (t & 1) * (NPAIR * KDIM);
        u64*       hnxt = hxb + ((t + 1) & 1) * (NPAIR * KDIM);

        // ---- matvec over KDIM=72 (h + x unified): 8 independent chains ----
        u64 a0[4], a1[4];
#pragma unroll
        for (int p = 0; p < 4; ++p) { a0[p] = bias0; a1[p] = bias1; }

#pragma unroll
        for (int kk = 0; kk < KK; ++kk) {
            const u64 w0a = wsm[(2 * kk) * 256 + g0];
            const u64 w0b = wsm[(2 * kk + 1) * 256 + g0];
            const u64 w1a = wsm[(2 * kk) * 256 + g1];
            const u64 w1b = wsm[(2 * kk + 1) * 256 + g1];
            ulonglong2 hv[4];
#pragma unroll
            for (int p = 0; p < 4; ++p)
                hv[p] = *(const ulonglong2*)(hcur + (4 * q + p) * KDIM + 2 * kk);
#pragma unroll
            for (int p = 0; p < 4; ++p) {
                a0[p] = ffma2(hv[p].x, w0a, a0[p]);
                a0[p] = ffma2(hv[p].y, w0b, a0[p]);
                a1[p] = ffma2(hv[p].x, w1a, a1[p]);
                a1[p] = ffma2(hv[p].y, w1b, a1[p]);
            }
        }

        // ---- exchange: write accs for FOREIGN pairs (partner = tid^32 owns them) ----
        gexch[0 * NTHR + tid] = a0[fi];
        gexch[1 * NTHR + tid] = a0[fi + 1];
        gexch[2 * NTHR + tid] = a1[fi];
        gexch[3 * NTHR + tid] = a1[fi + 1];

        // stash prefetched x into next buffer (not read until after barrier 2)
        if (do_x)
            ((float*)&hnxt[xp * KDIM + HDIM + xi])[xe] = xn;

        __syncthreads();   // barrier 1: gexch visible

        // ---- read partner's gate-half for OWN pairs ----
        const int ptid = tid ^ 32;
        const u64 pA0 = gexch[0 * NTHR + ptid];   // partner a0 for own pair 0
        const u64 pA1 = gexch[1 * NTHR + ptid];   // partner a0 for own pair 1
        const u64 pB0 = gexch[2 * NTHR + ptid];   // partner a1 for own pair 0
        const u64 pB1 = gexch[3 * NTHR + ptid];   // partner a1 for own pair 1

        // gate roles: gh==0 owns (i,f), partner supplies (g,o); gh==1 vice versa
        const u64 gI[2] = { gh ? pA0 : a0[oi],     gh ? pA1 : a0[oi + 1] };
        const u64 gF[2] = { gh ? pB0 : a1[oi],     gh ? pB1 : a1[oi + 1] };
        const u64 gG[2] = { gh ? a0[oi] : pA0,     gh ? a0[oi + 1] : pA1 };
        const u64 gO[2] = { gh ? a1[oi] : pB0,     gh ? a1[oi + 1] : pB1 };

        // ---- pointwise for own 2 pairs (4 batch elements) ----
#pragma unroll
        for (int s = 0; s < 2; ++s) {
            float ie, io, fe, fo, ge, go_, oe, oo;
            unpack2(gI[s], ie, io);
            unpack2(gF[s], fe, fo);
            unpack2(gG[s], ge, go_);
            unpack2(gO[s], oe, oo);

            float iv = sigm_f(ie), fv = sigm_f(fe), gv = tanh_f(ge), ov = sigm_f(oe);
            float c  = fmaf(fv, cc[s][0], iv * gv);
            cc[s][0] = c;
            float he = ov * tanh_f(c);

            iv = sigm_f(io); fv = sigm_f(fo); gv = tanh_f(go_); ov = sigm_f(oo);
            c  = fmaf(fv, cc[s][1], iv * gv);
            cc[s][1] = c;
            float ho = ov * tanh_f(c);

            hnxt[(4 * q + oi + s) * KDIM + u] = pack2(he, ho);
        }
        __syncthreads();   // barrier 2: h(t+1), x(t+1) visible
    }

    // ---- final FC: out[b] = h_T . Wfc + bfc ----
    const u64* hfin = hxb + (T & 1) * (NPAIR * KDIM);
    if (tid < nb) {
        const int p = tid >> 1, e = tid & 1;
        float s = bfc[0];
#pragma unroll
        for (int k = 0; k < HDIM; ++k)
            s = fmaf(((const float*)&hfin[p * KDIM + k])[e], Wfc[k], s);
        out[b0 + tid] = s;
    }
}

extern "C" void kernel_launch(void* const* d_in, const int* in_sizes, int n_in,
                              void* d_out, int out_size) {
    const float* x    = (const float*)d_in[0];
    const float* Wih  = (const float*)d_in[1];
    const float* Whh  = (const float*)d_in[2];
    const float* bih  = (const float*)d_in[3];
    const float* bhh  = (const float*)d_in[4];
    const float* Wfc  = (const float*)d_in[5];
    const float* bfc  = (const float*)d_in[6];
    float* out = (float*)d_out;

    const int B = out_size;                   // O = 1
    const int T = in_sizes[0] / (B * IDIM);

    cudaFuncSetAttribute(lstm_persistent_kernel,
                         cudaFuncAttributeMaxDynamicSharedMemorySize, SMEM_BYTES);

    const int grid = (B + NB - 1) / NB;
    lstm_persistent_kernel<<<grid, NTHR, SMEM_BYTES>>>(x, Wih, Whh, bih, bhh, Wfc, bfc, out, B, T);
}

// round 11
// speedup vs baseline: 1.2590x; 1.2590x over previous
#include <cuda_runtime.h>

typedef unsigned long long u64;

#define HDIM  64
#define IDIM  8
#define KDIM  72          // 64 h + 8 x folded into one reduction
#define KK    36          // KDIM/2
#define NTHR  128
#define NPAIR 8           // batch pairs per CTA
#define NB    16          // batches per CTA

// SMEM (dynamic), per CTA (must stay <= ~113KB for 2 CTAs/SM):
//  wsm2[kk=36][j=256] float2 {w[j][2kk], w[j][2kk+1]} : 73728 B  (scalar fp32, lane-consecutive)
//  hx[2][NPAIR][KDIM] u64 (h units 0..63, x 64..71)   :  9216 B
#define WSM2_BYTES (KK * 256 * 8)
#define HX_BYTES   (2 * NPAIR * KDIM * 8)
#define SMEM_BYTES (WSM2_BYTES + HX_BYTES)

// ---- packed f32x2 helpers (Blackwell sm_100a) ----
__device__ __forceinline__ u64 ffma2(u64 a, u64 b, u64 c) {
    u64 r;
    asm("fma.rn.f32x2 %0, %1, %2, %3;" : "=l"(r) : "l"(a), "l"(b), "l"(c));
    return r;
}
__device__ __forceinline__ u64 pack2(float x, float y) {
    u64 r;
    asm("mov.b64 %0, {%1, %2};" : "=l"(r) : "f"(x), "f"(y));
    return r;
}
__device__ __forceinline__ void unpack2(u64 v, float& lo, float& hi) {
    asm("mov.b64 {%0, %1}, %2;" : "=f"(lo), "=f"(hi) : "l"(v));
}

// ---- activations: __expf is MUFU-based, ~1e-7 rel err ----
__device__ __forceinline__ float sigm_f(float x) {
    return 1.0f / (1.0f + __expf(-x));
}
__device__ __forceinline__ float tanh_f(float x) {
    return fmaf(2.0f, 1.0f / (1.0f + __expf(-2.0f * x)), -1.0f);
}

__global__ void __launch_bounds__(NTHR, 2) lstm_persistent_kernel(
    const float* __restrict__ x,      // [B, T, I]
    const float* __restrict__ Wih,    // [4H, I]
    const float* __restrict__ Whh,    // [4H, H]
    const float* __restrict__ bih,    // [4H]
    const float* __restrict__ bhh,    // [4H]
    const float* __restrict__ Wfc,    // [1, H]
    const float* __restrict__ bfc,    // [1]
    float* __restrict__ out,          // [B, 1]
    int B, int T)
{
    extern __shared__ __align__(16) char smem_raw[];
    float2* wsm2 = (float2*)smem_raw;                 // [kk*256 + j]
    u64*    hxb  = (u64*)(smem_raw + WSM2_BYTES);     // [buf][pair][KDIM]

    const int tid = threadIdx.x;
    const int u   = tid & 63;         // hidden unit (lanes consecutive within warp)
    const int q   = tid >> 6;         // pair group 0/1 (warp-uniform)
    const int pb  = q * 4;            // first pair of this thread
    const int b0  = blockIdx.x * NB;
    const int nb  = min(NB, B - b0);
    const int nx  = nb * IDIM;        // = 128 for full CTAs

    // ---- stage combined W = [Whh | Wih] as scalar float2 per (kk, row) ----
    for (int idx = tid; idx < KK * 256; idx += NTHR) {
        const int kk = idx >> 8, j = idx & 255;
        const int k0 = 2 * kk, k1 = 2 * kk + 1;
        float wa = (k0 < HDIM) ? Whh[j * HDIM + k0] : Wih[j * IDIM + (k0 - HDIM)];
        float wb = (k1 < HDIM) ? Whh[j * HDIM + k1] : Wih[j * IDIM + (k1 - HDIM)];
        wsm2[idx] = make_float2(wa, wb);
    }

    // ---- per-thread biases for gate rows u, u+64, u+128, u+192 ----
    u64 bias2[4];
#pragma unroll
    for (int g = 0; g < 4; ++g) {
        float b = bih[u + 64 * g] + bhh[u + 64 * g];
        bias2[g] = pack2(b, b);
    }

    // ---- zero hx (both buffers) ----
    for (int idx = tid; idx < 2 * NPAIR * KDIM; idx += NTHR) hxb[idx] = 0ull;

    // ---- cell state in registers ----
    float ce[4], co[4];
#pragma unroll
    for (int p = 0; p < 4; ++p) { ce[p] = 0.0f; co[p] = 0.0f; }

    // ---- load x(t=0): 128 threads == 16 batches x 8 features ----
    int xp = 0, xe = 0, xi = 0;
    if (tid < nx) {
        xp = tid >> 4;            // pair 0..7
        xe = (tid >> 3) & 1;      // half within pair
        xi = tid & 7;             // feature
        float v = x[((size_t)(b0 + 2 * xp + xe) * T) * IDIM + xi];
        ((float*)&hxb[xp * KDIM + HDIM + xi])[xe] = v;
    }
    __syncthreads();

    for (int t = 0; t < T; ++t) {
        // prefetch x(t+1)
        float xn = 0.0f;
        const bool do_x = (t + 1 < T) && (tid < nx);
        if (do_x)
            xn = x[((size_t)(b0 + 2 * xp + xe) * T + (t + 1)) * IDIM + xi];

        const u64* hcur = hxb + (t & 1) * (NPAIR * KDIM);
        u64*       hnxt = hxb + ((t + 1) & 1) * (NPAIR * KDIM);

        // ---- matvec over KDIM=72: 16 independent chains ----
        u64 acc[4][4];
#pragma unroll
        for (int g = 0; g < 4; ++g)
#pragma unroll
            for (int p = 0; p < 4; ++p)
                acc[g][p] = bias2[g];

#pragma unroll
        for (int kk = 0; kk < KK; ++kk) {
            // weights: 4 LDS.64, lane-consecutive (2 phases each); pack on ALU pipe
            float2 wf[4];
#pragma unroll
            for (int g = 0; g < 4; ++g)
                wf[g] = wsm2[kk * 256 + u + 64 * g];
            u64 wA[4], wB[4];
#pragma unroll
            for (int g = 0; g < 4; ++g) {
                wA[g] = pack2(wf[g].x, wf[g].x);
                wB[g] = pack2(wf[g].y, wf[g].y);
            }
            // h: 4 LDS.128 broadcast (1 phase each)
            ulonglong2 hv[4];
#pragma unroll
            for (int p = 0; p < 4; ++p)
                hv[p] = *(const ulonglong2*)(hcur + (pb + p) * KDIM + 2 * kk);
#pragma unroll
            for (int p = 0; p < 4; ++p) {
#pragma unroll
                for (int g = 0; g < 4; ++g) {
                    u64 a = acc[g][p];
                    a = ffma2(hv[p].x, wA[g], a);
                    a = ffma2(hv[p].y, wB[g], a);
                    acc[g][p] = a;
                }
            }
        }

        // stash prefetched x into next buffer (read after barrier)
        if (do_x)
            ((float*)&hnxt[xp * KDIM + HDIM + xi])[xe] = xn;

        // ---- pointwise IN REGISTERS: i,f,g,o -> c,h ----
#pragma unroll
        for (int p = 0; p < 4; ++p) {
            float gie, gio, gfe, gfo, gge, ggo, goe, goo;
            unpack2(acc[0][p], gie, gio);
            unpack2(acc[1][p], gfe, gfo);
            unpack2(acc[2][p], gge, ggo);
            unpack2(acc[3][p], goe, goo);

            float iv = sigm_f(gie);
            float fv = sigm_f(gfe);
            float gv = tanh_f(gge);
            float ov = sigm_f(goe);
            float c  = fmaf(fv, ce[p], iv * gv);
            ce[p] = c;
            float he = ov * tanh_f(c);

            iv = sigm_f(gio);
            fv = sigm_f(gfo);
            gv = tanh_f(ggo);
            ov = sigm_f(goo);
            c  = fmaf(fv, co[p], iv * gv);
            co[p] = c;
            float ho = ov * tanh_f(c);

            hnxt[(pb + p) * KDIM + u] = pack2(he, ho);
        }
        __syncthreads();   // single barrier per step
    }

    // ---- final FC: out[b] = h_T . Wfc + bfc ----
    const u64* hfin = hxb + (T & 1) * (NPAIR * KDIM);
    if (tid < nb) {
        const int p = tid >> 1, e = tid & 1;
        float s = bfc[0];
#pragma unroll
        for (int k = 0; k < HDIM; ++k)
            s = fmaf(((const float*)&hfin[p * KDIM + k])[e], Wfc[k], s);
        out[b0 + tid] = s;
    }
}

extern "C" void kernel_launch(void* const* d_in, const int* in_sizes, int n_in,
                              void* d_out, int out_size) {
    const float* x    = (const float*)d_in[0];
    const float* Wih  = (const float*)d_in[1];
    const float* Whh  = (const float*)d_in[2];
    const float* bih  = (const float*)d_in[3];
    const float* bhh  = (const float*)d_in[4];
    const float* Wfc  = (const float*)d_in[5];
    const float* bfc  = (const float*)d_in[6];
    float* out = (float*)d_out;

    const int B = out_size;                   // O = 1
    const int T = in_sizes[0] / (B * IDIM);

    cudaFuncSetAttribute(lstm_persistent_kernel,
                         cudaFuncAttributeMaxDynamicSharedMemorySize, SMEM_BYTES);

    const int grid = (B + NB - 1) / NB;       // 256 CTAs -> 2 per SM
    lstm_persistent_kernel<<<grid, NTHR, SMEM_BYTES>>>(x, Wih, Whh, bih, bhh, Wfc, bfc, out, B, T);
}